// round 7
// baseline (speedup 1.0000x reference)
#include <cuda_runtime.h>
#include <math_constants.h>
#include <cstdint>

// FLoss: weighted BCE, weights = W / (dist_to_argmax_centroid + 1)
// input  d_in[0]: [B,1,T,W,W] f32  (same linear layout as [B,T,W,W])
// target d_in[1]: [B,T,W,W]   f32
// out: scalar f32 = -mean(w * (t*clip(log p,-100) + (1-t)*clip(log1p(-p),-100)))

#define FRAME_ELEMS4 16384                 // 65536 elems / 4
#define MAX_FRAMES 4096

__device__ float2   g_c[MAX_FRAMES];       // packed (cx, cy) per frame
__device__ double   g_acc;
__device__ unsigned g_done;

#define LOG2_CLAMP (-144.26950408889634f)  // -100 / ln(2)
#define LN2F        (0.6931471805599453f)

// ---------------------------------------------------------------------------
// Kernel 1: per-frame max + centroid, single pass, branchless 4-chain.
// One CTA (1024 threads) per frame. Measured ~7.6 TB/s — at roofline.
// Exact tie semantics (target == max), identical to reference.
// ---------------------------------------------------------------------------
__global__ __launch_bounds__(1024) void frame_stats_kernel(const float* __restrict__ tgt)
{
    const int f   = blockIdx.x;
    const int tid = threadIdx.x;
    const float4* base = reinterpret_cast<const float4*>(tgt) + (size_t)f * FRAME_ELEMS4;

    float lm[4], cn[4], sx[4], sy[4];
    #pragma unroll
    for (int c = 0; c < 4; c++) { lm[c] = -CUDART_INF_F; cn[c] = 0.f; sx[c] = 0.f; sy[c] = 0.f; }

    #pragma unroll
    for (int k = 0; k < 16; k++) {
        const int e4 = tid + k * 1024;
        const float4 v = __ldg(base + e4);
        const int e = e4 * 4;
        const float row  = (float)(e >> 8);
        const float col0 = (float)(e & 255);
        const float vals[4] = {v.x, v.y, v.z, v.w};
        #pragma unroll
        for (int c = 0; c < 4; c++) {
            const float val = vals[c];
            const float col = col0 + (float)c;
            const bool gt = (val >  lm[c]);
            const bool eq = (val == lm[c]);
            cn[c] = gt ? 1.f : (cn[c] + (eq ? 1.f : 0.f));
            sx[c] = gt ? row : (sx[c] + (eq ? row : 0.f));
            sy[c] = gt ? col : (sy[c] + (eq ? col : 0.f));
            lm[c] = fmaxf(lm[c], val);
        }
    }

    float lmax = lm[0], cnt = cn[0], tsx = sx[0], tsy = sy[0];
    #pragma unroll
    for (int c = 1; c < 4; c++) {
        if (lm[c] > lmax)       { lmax = lm[c]; cnt = cn[c]; tsx = sx[c]; tsy = sy[c]; }
        else if (lm[c] == lmax) { cnt += cn[c]; tsx += sx[c]; tsy += sy[c]; }
    }

    __shared__ float s_wmax[32];
    __shared__ float s_gmax, s_sx, s_sy, s_cnt;

    float wm = lmax;
    #pragma unroll
    for (int o = 16; o; o >>= 1) wm = fmaxf(wm, __shfl_xor_sync(0xffffffffu, wm, o));
    if ((tid & 31) == 0) s_wmax[tid >> 5] = wm;
    if (tid == 0) { s_sx = 0.f; s_sy = 0.f; s_cnt = 0.f; }
    __syncthreads();
    if (tid < 32) {
        float m = s_wmax[tid];
        #pragma unroll
        for (int o = 16; o; o >>= 1) m = fmaxf(m, __shfl_xor_sync(0xffffffffu, m, o));
        if (tid == 0) s_gmax = m;
    }
    __syncthreads();

    if (lmax == s_gmax) {
        atomicAdd(&s_cnt, cnt);
        atomicAdd(&s_sx,  tsx);
        atomicAdd(&s_sy,  tsy);
    }
    __syncthreads();

    if (tid == 0) {
        g_c[f] = make_float2(s_sx / s_cnt, s_sy / s_cnt);
        if (f == 0) { g_acc = 0.0; g_done = 0u; }   // per-replay reset (before loss)
    }
}

// ---------------------------------------------------------------------------
// Kernel 2: weighted BCE. Grid-stride, 4-wide, 32 regs / 83% occupancy
// (the measured-best configuration). Last CTA finalizes the scalar.
// ---------------------------------------------------------------------------
__global__ __launch_bounds__(256, 8) void loss_kernel(const float* __restrict__ inp,
                                                      const float* __restrict__ tgt,
                                                      int total4,
                                                      float* __restrict__ out,
                                                      double inv_n)
{
    __shared__ double s_acc;
    if (threadIdx.x == 0) s_acc = 0.0;
    __syncthreads();

    const float4* P = reinterpret_cast<const float4*>(inp);
    const float4* T = reinterpret_cast<const float4*>(tgt);

    float lsum = 0.f;
    const int stride = gridDim.x * blockDim.x;
    for (int i = blockIdx.x * blockDim.x + threadIdx.x; i < total4; i += stride) {
        const float2 cc = __ldg(&g_c[i >> 14]);        // frame centroid (L1/L2 hit)

        const float4 p4 = __ldcs(P + i);               // streaming
        const float4 t4 = __ldg (T + i);

        const float row  = (float)((i >> 6) & 255);
        const float col0 = (float)((i & 63) * 4);
        const float di   = row - cc.x;
        const float di2  = di * di;

        const float pv[4] = {p4.x, p4.y, p4.z, p4.w};
        const float tv[4] = {t4.x, t4.y, t4.z, t4.w};

        #pragma unroll
        for (int c = 0; c < 4; c++) {
            const float dj = (col0 + (float)c) - cc.y;
            const float s  = fmaf(dj, dj, di2);
            float dist, wrcp;
            asm("sqrt.approx.f32 %0, %1;" : "=f"(dist) : "f"(s));    // sqrt.approx(0)=0
            asm("rcp.approx.f32 %0, %1;"  : "=f"(wrcp) : "f"(dist + 1.0f));
            const float wgt = 256.0f * wrcp;

            const float p = pv[c];
            const float t = tv[c];
            float lp2, lq2;
            asm("lg2.approx.f32 %0, %1;" : "=f"(lp2) : "f"(p));
            asm("lg2.approx.f32 %0, %1;" : "=f"(lq2) : "f"(1.0f - p));
            lp2 = fmaxf(lp2, LOG2_CLAMP);
            lq2 = fmaxf(lq2, LOG2_CLAMP);
            const float term = fmaf(t, lp2 - lq2, lq2);   // log2 domain
            lsum = fmaf(wgt, term, lsum);
        }
    }
    lsum *= LN2F;

    #pragma unroll
    for (int o = 16; o; o >>= 1) lsum += __shfl_xor_sync(0xffffffffu, lsum, o);
    if ((threadIdx.x & 31) == 0) atomicAdd(&s_acc, (double)lsum);
    __syncthreads();

    if (threadIdx.x == 0) {
        atomicAdd(&g_acc, s_acc);
        __threadfence();
        const unsigned t = atomicAdd(&g_done, 1u);
        if (t == gridDim.x - 1) {
            const double total = atomicAdd(&g_acc, 0.0);
            out[0] = (float)(-total * inv_n);
        }
    }
}

extern "C" void kernel_launch(void* const* d_in, const int* in_sizes, int n_in,
                              void* d_out, int out_size)
{
    const float* inp = (const float*)d_in[0];
    const float* tgt = (const float*)d_in[1];
    float* out = (float*)d_out;

    const int n       = in_sizes[1];       // B*T*W*W
    const int nframes = n >> 16;
    const int total4  = n >> 2;

    frame_stats_kernel<<<nframes, 1024>>>(tgt);

    const int grid = 148 * 16;             // 2368 CTAs x 256 thr
    loss_kernel<<<grid, 256>>>(inp, tgt, total4, out, 1.0 / (double)n);
}

// round 8
// speedup vs baseline: 1.0602x; 1.0602x over previous
#include <cuda_runtime.h>
#include <math_constants.h>
#include <cstdint>

// FLoss: weighted BCE, weights = W / (dist_to_argmax_centroid + 1)
// input  d_in[0]: [B,1,T,W,W] f32  (same linear layout as [B,T,W,W])
// target d_in[1]: [B,T,W,W]   f32
// out: scalar f32 = -mean(w * (t*clip(log p,-100) + (1-t)*clip(log1p(-p),-100)))
//
// Single fused kernel: one 512-thread CTA per 256x256 frame, 2 CTAs/SM.
// Pass A: max+centroid in ONE scan (branchless running chains).
// Pass B: loss; target re-read hits L2 (all frames resident), input streamed.

#define FRAME_ELEMS4 16384                 // 65536 elems / 4

__device__ double   g_acc;                 // zero-init; last CTA resets each replay
__device__ unsigned g_done;

#define LOG2_CLAMP (-144.26950408889634f)  // -100 / ln(2)
#define LN2F        (0.6931471805599453f)

__global__ __launch_bounds__(512, 2) void floss_fused_kernel(const float* __restrict__ inp,
                                                             const float* __restrict__ tgt,
                                                             float* __restrict__ out,
                                                             double inv_n)
{
    const int f   = blockIdx.x;
    const int tid = threadIdx.x;
    const float4* T = reinterpret_cast<const float4*>(tgt) + (size_t)f * FRAME_ELEMS4;
    const float4* P = reinterpret_cast<const float4*>(inp) + (size_t)f * FRAME_ELEMS4;

    // ---------------- Pass A: max + centroid of maximal pixels, one scan ----
    // 4 independent branchless running chains (exact target==max semantics).
    float lm[4], cn[4], sx[4], sy[4];
    #pragma unroll
    for (int c = 0; c < 4; c++) { lm[c] = -CUDART_INF_F; cn[c] = 0.f; sx[c] = 0.f; sy[c] = 0.f; }

    #pragma unroll 8
    for (int k = 0; k < 32; k++) {
        const int e4 = tid + k * 512;
        const float4 v = __ldg(T + e4);
        const int e = e4 * 4;
        const float row  = (float)(e >> 8);
        const float col0 = (float)(e & 255);
        const float vals[4] = {v.x, v.y, v.z, v.w};
        #pragma unroll
        for (int c = 0; c < 4; c++) {
            const float val = vals[c];
            const float col = col0 + (float)c;
            const bool gt = (val >  lm[c]);
            const bool eq = (val == lm[c]);
            cn[c] = gt ? 1.f : (cn[c] + (eq ? 1.f : 0.f));
            sx[c] = gt ? row : (sx[c] + (eq ? row : 0.f));
            sy[c] = gt ? col : (sy[c] + (eq ? col : 0.f));
            lm[c] = fmaxf(lm[c], val);
        }
    }

    float lmax = lm[0], cnt = cn[0], tsx = sx[0], tsy = sy[0];
    #pragma unroll
    for (int c = 1; c < 4; c++) {
        if (lm[c] > lmax)       { lmax = lm[c]; cnt = cn[c]; tsx = sx[c]; tsy = sy[c]; }
        else if (lm[c] == lmax) { cnt += cn[c]; tsx += sx[c]; tsy += sy[c]; }
    }

    __shared__ float s_wmax[16];
    __shared__ float s_gmax, s_sx, s_sy, s_cnt, s_cx, s_cy;

    float wm = lmax;
    #pragma unroll
    for (int o = 16; o; o >>= 1) wm = fmaxf(wm, __shfl_xor_sync(0xffffffffu, wm, o));
    if ((tid & 31) == 0) s_wmax[tid >> 5] = wm;
    if (tid == 0) { s_sx = 0.f; s_sy = 0.f; s_cnt = 0.f; }
    __syncthreads();
    if (tid < 32) {
        float m = (tid < 16) ? s_wmax[tid] : -CUDART_INF_F;
        #pragma unroll
        for (int o = 8; o; o >>= 1) m = fmaxf(m, __shfl_xor_sync(0xffffffffu, m, o));
        if (tid == 0) s_gmax = m;
    }
    __syncthreads();

    if (lmax == s_gmax) {            // rare: only threads holding the frame max
        atomicAdd(&s_cnt, cnt);
        atomicAdd(&s_sx,  tsx);
        atomicAdd(&s_sy,  tsy);
    }
    __syncthreads();
    if (tid == 0) { s_cx = s_sx / s_cnt; s_cy = s_sy / s_cnt; }
    __syncthreads();
    const float cx = s_cx;
    const float cy = s_cy;

    // ---------------- Pass B: weighted BCE --------------------------------
    // Geometry hoisting: 512 threads cover 8 rows x 64 float4-cols per step;
    // column (and dj^2) is loop-invariant per thread, row advances by 8.
    const float col0 = (float)((tid & 63) * 4);
    float dj2[4];
    #pragma unroll
    for (int c = 0; c < 4; c++) {
        const float dj = (col0 + (float)c) - cy;
        dj2[c] = dj * dj;
    }
    float di = (float)(tid >> 6) - cx;     // row - cx, advances by +8 per iter

    float lsum = 0.f;
    #pragma unroll 4
    for (int k = 0; k < 32; k++) {
        const int e4 = tid + k * 512;
        const float4 t4 = __ldg (T + e4);      // L2 hit (frame resident)
        const float4 p4 = __ldcs(P + e4);      // DRAM stream, evict-first

        const float di2 = di * di;
        di += 8.0f;

        const float pv[4] = {p4.x, p4.y, p4.z, p4.w};
        const float tv[4] = {t4.x, t4.y, t4.z, t4.w};

        #pragma unroll
        for (int c = 0; c < 4; c++) {
            const float s = di2 + dj2[c];
            float dist, wrcp;
            asm("sqrt.approx.f32 %0, %1;" : "=f"(dist) : "f"(s));    // sqrt.approx(0)=0
            asm("rcp.approx.f32 %0, %1;"  : "=f"(wrcp) : "f"(dist + 1.0f));
            const float wgt = 256.0f * wrcp;

            const float p = pv[c];
            const float t = tv[c];
            float lp2, lq2;
            asm("lg2.approx.f32 %0, %1;" : "=f"(lp2) : "f"(p));
            asm("lg2.approx.f32 %0, %1;" : "=f"(lq2) : "f"(1.0f - p));
            lp2 = fmaxf(lp2, LOG2_CLAMP);
            lq2 = fmaxf(lq2, LOG2_CLAMP);
            const float term = fmaf(t, lp2 - lq2, lq2);   // log2 domain
            lsum = fmaf(wgt, term, lsum);
        }
    }
    lsum *= LN2F;

    // ---------------- reduce + last-CTA finalize ---------------------------
    __shared__ double s_acc;
    if (tid == 0) s_acc = 0.0;
    __syncthreads();

    #pragma unroll
    for (int o = 16; o; o >>= 1) lsum += __shfl_xor_sync(0xffffffffu, lsum, o);
    if ((tid & 31) == 0) atomicAdd(&s_acc, (double)lsum);
    __syncthreads();

    if (tid == 0) {
        atomicAdd(&g_acc, s_acc);
        __threadfence();
        const unsigned tk = atomicAdd(&g_done, 1u);
        if (tk == gridDim.x - 1) {             // last CTA of this replay
            const double total = atomicAdd(&g_acc, 0.0);
            out[0] = (float)(-total * inv_n);
            g_acc = 0.0;                       // reset for next graph replay
            __threadfence();
            atomicExch(&g_done, 0u);
        }
    }
}

extern "C" void kernel_launch(void* const* d_in, const int* in_sizes, int n_in,
                              void* d_out, int out_size)
{
    const float* inp = (const float*)d_in[0];
    const float* tgt = (const float*)d_in[1];
    float* out = (float*)d_out;

    const int n       = in_sizes[1];       // B*T*W*W
    const int nframes = n >> 16;           // 65536 elems per frame

    floss_fused_kernel<<<nframes, 512>>>(inp, tgt, out, 1.0 / (double)n);
}

// round 9
// speedup vs baseline: 1.1155x; 1.0522x over previous
#include <cuda_runtime.h>
#include <math_constants.h>
#include <cstdint>

// FLoss: weighted BCE, weights = W / (dist_to_argmax_centroid + 1)
// input  d_in[0]: [B,1,T,W,W] f32  (same linear layout as [B,T,W,W])
// target d_in[1]: [B,T,W,W]   f32
// out: scalar f32 = -mean(w * (t*clip(log p,-100) + (1-t)*clip(log1p(-p),-100)))
//
// Fused, one 1024-thread CTA per frame, 2 CTAs/SM (32-reg cap).
//   pass 1: frame max only (FMNMX), forward — fills L1/L2
//   pass 2: centroid of argmax pixels, REVERSE rescan (L1-resident tail)
//   pass 3: weighted BCE forward; target re-read warm, input streamed (.cs)

#define FRAME_ELEMS4 16384                 // 65536 elems / 4

__device__ double   g_acc;                 // zero-init; last CTA resets each replay
__device__ unsigned g_done;

#define LOG2_CLAMP (-144.26950408889634f)  // -100 / ln(2)
#define LN2F        (0.6931471805599453f)

__global__ __launch_bounds__(1024, 2) void floss_fused_kernel(const float* __restrict__ inp,
                                                              const float* __restrict__ tgt,
                                                              float* __restrict__ out,
                                                              double inv_n)
{
    const int f   = blockIdx.x;
    const int tid = threadIdx.x;
    const float4* T = reinterpret_cast<const float4*>(tgt) + (size_t)f * FRAME_ELEMS4;
    const float4* P = reinterpret_cast<const float4*>(inp) + (size_t)f * FRAME_ELEMS4;

    __shared__ float s_wmax[32];
    __shared__ float s_gmax, s_sx, s_sy, s_cnt, s_cx, s_cy;

    // ---------------- pass 1: frame max only (cheap, 4 FMNMX/iter) ---------
    float m0 = -CUDART_INF_F, m1 = -CUDART_INF_F, m2 = -CUDART_INF_F, m3 = -CUDART_INF_F;
    #pragma unroll 4
    for (int k = 0; k < 16; k++) {
        const float4 v = __ldg(T + tid + k * 1024);
        m0 = fmaxf(m0, v.x); m1 = fmaxf(m1, v.y);
        m2 = fmaxf(m2, v.z); m3 = fmaxf(m3, v.w);
    }
    float lmax = fmaxf(fmaxf(m0, m1), fmaxf(m2, m3));

    #pragma unroll
    for (int o = 16; o; o >>= 1) lmax = fmaxf(lmax, __shfl_xor_sync(0xffffffffu, lmax, o));
    if ((tid & 31) == 0) s_wmax[tid >> 5] = lmax;
    if (tid == 0) { s_sx = 0.f; s_sy = 0.f; s_cnt = 0.f; }
    __syncthreads();
    if (tid < 32) {
        float m = s_wmax[tid];
        #pragma unroll
        for (int o = 16; o; o >>= 1) m = fmaxf(m, __shfl_xor_sync(0xffffffffu, m, o));
        if (tid == 0) s_gmax = m;
    }
    __syncthreads();

    // ---------------- pass 2: centroid (reverse scan, rare atomics) --------
    // Exact float-equality mask, identical to reference (target == max).
    const float gmax = s_gmax;
    #pragma unroll 4
    for (int k = 15; k >= 0; k--) {
        const int e4 = tid + k * 1024;
        const float4 v = __ldg(T + e4);
        const float vm = fmaxf(fmaxf(v.x, v.y), fmaxf(v.z, v.w));
        if (vm == gmax) {                         // rare path
            const int e = e4 * 4;
            const float row  = (float)(e >> 8);
            const float col0 = (float)(e & 255);
            if (v.x == gmax) { atomicAdd(&s_cnt, 1.f); atomicAdd(&s_sx, row); atomicAdd(&s_sy, col0); }
            if (v.y == gmax) { atomicAdd(&s_cnt, 1.f); atomicAdd(&s_sx, row); atomicAdd(&s_sy, col0 + 1.f); }
            if (v.z == gmax) { atomicAdd(&s_cnt, 1.f); atomicAdd(&s_sx, row); atomicAdd(&s_sy, col0 + 2.f); }
            if (v.w == gmax) { atomicAdd(&s_cnt, 1.f); atomicAdd(&s_sx, row); atomicAdd(&s_sy, col0 + 3.f); }
        }
    }
    __syncthreads();
    if (tid == 0) { s_cx = s_sx / s_cnt; s_cy = s_sy / s_cnt; }
    __syncthreads();
    const float cx = s_cx;
    const float cy = s_cy;

    // ---------------- pass 3: weighted BCE (forward) -----------------------
    // 1024 threads = 16 rows x 64 float4-cols per step; row advances by 16.
    const float col0 = (float)((tid & 63) * 4) - cy;   // dj for lane c: col0 + c
    float di = (float)(tid >> 6) - cx;

    float lsum = 0.f;
    #pragma unroll 2
    for (int k = 0; k < 16; k++) {
        const int e4 = tid + k * 1024;
        const float4 t4 = __ldg (T + e4);       // warm (L1/L2)
        const float4 p4 = __ldcs(P + e4);       // DRAM stream, evict-first

        const float di2 = di * di;
        di += 16.0f;

        #pragma unroll
        for (int c = 0; c < 4; c++) {
            const float p = (c == 0) ? p4.x : (c == 1) ? p4.y : (c == 2) ? p4.z : p4.w;
            const float t = (c == 0) ? t4.x : (c == 1) ? t4.y : (c == 2) ? t4.z : t4.w;

            const float dj = col0 + (float)c;
            const float s  = fmaf(dj, dj, di2);
            float dist, wrcp;
            asm("sqrt.approx.f32 %0, %1;" : "=f"(dist) : "f"(s));   // sqrt.approx(0)=0
            asm("rcp.approx.f32 %0, %1;"  : "=f"(wrcp) : "f"(dist + 1.0f));

            float lp2, lq2;
            asm("lg2.approx.f32 %0, %1;" : "=f"(lp2) : "f"(p));
            asm("lg2.approx.f32 %0, %1;" : "=f"(lq2) : "f"(1.0f - p));
            lp2 = fmaxf(lp2, LOG2_CLAMP);
            lq2 = fmaxf(lq2, LOG2_CLAMP);
            const float term = fmaf(t, lp2 - lq2, lq2);     // log2 domain
            lsum = fmaf(256.0f * wrcp, term, lsum);
        }
    }
    lsum *= LN2F;

    // ---------------- reduce + last-CTA finalize ---------------------------
    __shared__ double s_acc;
    if (tid == 0) s_acc = 0.0;
    __syncthreads();

    #pragma unroll
    for (int o = 16; o; o >>= 1) lsum += __shfl_xor_sync(0xffffffffu, lsum, o);
    if ((tid & 31) == 0) atomicAdd(&s_acc, (double)lsum);
    __syncthreads();

    if (tid == 0) {
        atomicAdd(&g_acc, s_acc);
        __threadfence();
        const unsigned tk = atomicAdd(&g_done, 1u);
        if (tk == gridDim.x - 1) {                // last CTA of this replay
            const double total = atomicAdd(&g_acc, 0.0);
            out[0] = (float)(-total * inv_n);
            g_acc = 0.0;                          // reset for next graph replay
            __threadfence();
            atomicExch(&g_done, 0u);
        }
    }
}

extern "C" void kernel_launch(void* const* d_in, const int* in_sizes, int n_in,
                              void* d_out, int out_size)
{
    const float* inp = (const float*)d_in[0];
    const float* tgt = (const float*)d_in[1];
    float* out = (float*)d_out;

    const int n       = in_sizes[1];       // B*T*W*W
    const int nframes = n >> 16;           // 65536 elems per frame

    floss_fused_kernel<<<nframes, 1024>>>(inp, tgt, out, 1.0 / (double)n);
}